// round 6
// baseline (speedup 1.0000x reference)
#include <cuda_runtime.h>
#include <math.h>
#include <stdint.h>

// ---------------------------------------------------------------------------
// Net_66468913873438: GCN(512->64)+ReLU -> GatedGraphConv(H=64, 2 layers)
//                     -> GCN(64->16) -> log_softmax
// N = 100000, E = 3200000.
// R6: overlap gh-GEMM with gather (heterogeneous interleaved grid),
//     prefetch-pipelined K=512 GEMM (launched at ncu slot 4),
//     single-B-load K=64 GEMM, parallel chunk-sum scan.
// ---------------------------------------------------------------------------

#define NMAX 100000
#define EMAX 3200000
#define CHUNK 1024

// Scratch (static device globals).
__device__ __align__(16) float  g_deg   [NMAX];
__device__ __align__(16) float  g_dinv  [NMAX];
__device__ __align__(16) float  g_hs    [NMAX * 64];   // gemm1 out / msg buffer
__device__ __align__(16) float  g_acc   [NMAX * 64];   // gather accumulator
__device__ __align__(16) float  g_x     [NMAX * 64];   // node state
__device__ __align__(16) float  g_hs3   [NMAX * 16];
__device__ __align__(16) float  g_gi    [NMAX * 192];
__device__ __align__(16) float  g_gh    [NMAX * 192];
__device__ __align__(16) float  g_W1T   [64 * 512];
__device__ __align__(16) float  g_WgT   [2 * 64 * 64];
// CSR
__device__ __align__(16) int    g_cnt   [NMAX];
__device__ __align__(16) int    g_start [NMAX];
__device__ __align__(16) int    g_cursor[NMAX];
__device__ __align__(16) int    g_csum  [128];
__device__ __align__(16) float2 g_sw    [EMAX];   // (src as int bits, weight)

// ---------------------------------------------------------------------------
// tf32 mma.sync helpers (sm_80 base ISA)
// ---------------------------------------------------------------------------
__device__ __forceinline__ float fhi(float a) {
    return __int_as_float(__float_as_int(a) & 0xFFFFE000u);
}

struct AFrag { uint32_t h[4]; uint32_t l[4]; };

__device__ __forceinline__ void mma8(float c[4], const uint32_t a[4],
                                     uint32_t b0, uint32_t b1) {
    asm volatile(
        "mma.sync.aligned.m16n8k8.row.col.f32.tf32.tf32.f32 "
        "{%0,%1,%2,%3}, {%4,%5,%6,%7}, {%8,%9}, {%0,%1,%2,%3};"
        : "+f"(c[0]), "+f"(c[1]), "+f"(c[2]), "+f"(c[3])
        : "r"(a[0]), "r"(a[1]), "r"(a[2]), "r"(a[3]), "r"(b0), "r"(b1));
}

__device__ __forceinline__ void load_afrag(const float* As, int stride, int rbase,
                                           int k0, int g, int tg, AFrag& f) {
    float a0 = As[(rbase + g) * stride + k0 + tg];
    float a1 = As[(rbase + g + 8) * stride + k0 + tg];
    float a2 = As[(rbase + g) * stride + k0 + tg + 4];
    float a3 = As[(rbase + g + 8) * stride + k0 + tg + 4];
    float h0 = fhi(a0), h1 = fhi(a1), h2 = fhi(a2), h3 = fhi(a3);
    f.h[0] = __float_as_uint(h0); f.l[0] = __float_as_uint(fhi(a0 - h0));
    f.h[1] = __float_as_uint(h1); f.l[1] = __float_as_uint(fhi(a1 - h1));
    f.h[2] = __float_as_uint(h2); f.l[2] = __float_as_uint(fhi(a2 - h2));
    f.h[3] = __float_as_uint(h3); f.l[3] = __float_as_uint(fhi(a3 - h3));
}

// one k8 step: warp tile 32 rows (2 m-frags) x 64 cols (8 n-frags), tf32x3.
__device__ __forceinline__ void mma_step(const float* As, int astride, int wr,
                                         int ak0, const float* Bh, const float* Bl,
                                         int bstride, int bk0,
                                         int g, int tg, float c[2][8][4]) {
    AFrag fa[2];
    load_afrag(As, astride, wr, ak0, g, tg, fa[0]);
    load_afrag(As, astride, wr + 16, ak0, g, tg, fa[1]);
#pragma unroll
    for (int nt = 0; nt < 8; nt++) {
        int nr = (nt * 8 + g) * bstride + bk0;
        uint32_t bh0 = __float_as_uint(Bh[nr + tg]);
        uint32_t bh1 = __float_as_uint(Bh[nr + tg + 4]);
        uint32_t bl0 = __float_as_uint(Bl[nr + tg]);
        uint32_t bl1 = __float_as_uint(Bl[nr + tg + 4]);
#pragma unroll
        for (int mt = 0; mt < 2; mt++) {
            mma8(c[mt][nt], fa[mt].h, bh0, bh1);
            mma8(c[mt][nt], fa[mt].l, bh0, bh1);
            mma8(c[mt][nt], fa[mt].h, bl0, bl1);
        }
    }
}

// ---------------------------------------------------------------------------
// Small utility kernels
// ---------------------------------------------------------------------------
__global__ void k_init(float* __restrict__ deg, int* __restrict__ cnt, int n) {
    int i = blockIdx.x * 256 + threadIdx.x;
    if (i < n) { deg[i] = 1.0f; cnt[i] = 0; }
}
__global__ void k_deg_hist(const int* __restrict__ col, const float* __restrict__ w,
                           float* __restrict__ deg, int* __restrict__ cnt, int E) {
    int e = blockIdx.x * 256 + threadIdx.x;
    if (e < E) {
        int d = col[e];
        atomicAdd(&deg[d], w[e]);
        atomicAdd(&cnt[d], 1);
    }
}
__global__ void k_dinv(const float* __restrict__ deg, float* __restrict__ dinv, int n) {
    int i = blockIdx.x * 256 + threadIdx.x;
    if (i < n) {
        float d = deg[i];
        dinv[i] = (d > 0.f) ? rsqrtf(d) : 0.f;
    }
}
__global__ void k_T512(const float* __restrict__ W, float* __restrict__ WT) {
    int idx = blockIdx.x * 256 + threadIdx.x;
    if (idx >= 512 * 64) return;
    int k = idx / 64, j = idx % 64;
    WT[j * 512 + k] = W[idx];
}
__global__ void k_T64(const float* __restrict__ Wg, float* __restrict__ WgT) {
    int idx = blockIdx.x * 256 + threadIdx.x;
    if (idx >= 2 * 64 * 64) return;
    int l = idx / 4096;
    int rem = idx % 4096;
    int k = rem / 64, j = rem % 64;
    WgT[l * 4096 + j * 64 + k] = Wg[idx];
}

// ---------------------------------------------------------------------------
// CSR build
// ---------------------------------------------------------------------------
__global__ void k_scan_chunk(const int* __restrict__ cnt, int* __restrict__ start,
                             int* __restrict__ csum, int n) {
    __shared__ int sm[CHUNK];
    int base = blockIdx.x * CHUNK;
    int t = threadIdx.x;
    int v = (base + t < n) ? cnt[base + t] : 0;
    sm[t] = v;
    __syncthreads();
#pragma unroll
    for (int off = 1; off < CHUNK; off <<= 1) {
        int x = (t >= off) ? sm[t - off] : 0;
        __syncthreads();
        sm[t] += x;
        __syncthreads();
    }
    if (base + t < n) start[base + t] = sm[t] - v;
    if (t == CHUNK - 1) csum[blockIdx.x] = sm[t];
}
// exclusive scan of chunk sums (nch <= 128), one block of 128 threads
__global__ void k_scan_sums(int* __restrict__ csum, int nch) {
    __shared__ int s[128];
    int t = threadIdx.x;
    int v = (t < nch) ? csum[t] : 0;
    s[t] = v;
    __syncthreads();
#pragma unroll
    for (int off = 1; off < 128; off <<= 1) {
        int x = (t >= off) ? s[t - off] : 0;
        __syncthreads();
        s[t] += x;
        __syncthreads();
    }
    if (t < nch) csum[t] = s[t] - v;
}
__global__ void k_scan_add(int* __restrict__ start, int* __restrict__ cursor,
                           const int* __restrict__ csum, int n) {
    int i = blockIdx.x * 256 + threadIdx.x;
    if (i < n) {
        int s = start[i] + csum[i >> 10];
        start[i] = s;
        cursor[i] = s;
    }
}
__global__ void k_reorder(const int* __restrict__ row, const int* __restrict__ col,
                          const float* __restrict__ w, int* __restrict__ cursor,
                          float2* __restrict__ sw, int E) {
    int e = blockIdx.x * 256 + threadIdx.x;
    if (e >= E) return;
    int d = col[e];
    int pos = atomicAdd(&cursor[d], 1);
    sw[pos] = make_float2(__int_as_float(row[e]), w[e]);
}

// ---------------------------------------------------------------------------
// tf32x3 GEMM, K=512, prefetch-pipelined:
// hs[m,j] = rsqrt(deg[m]) * sum_k A[m,k] W1T[j,k]
// ---------------------------------------------------------------------------
#define K512_SMEM ((256 * 36 + 2 * 64 * 36) * 4)

__global__ __launch_bounds__(256) void mma_k512(
    const float4* __restrict__ A4, const float4* __restrict__ B4,
    float* __restrict__ out, const float* __restrict__ deg, int M)
{
    extern __shared__ float sm[];
    float* As = sm;
    float* Bh = sm + 256 * 36;
    float* Bl = Bh + 64 * 36;

    int tid = threadIdx.x, wid = tid >> 5, lane = tid & 31;
    int g = lane >> 2, tg = lane & 3;
    int blk = blockIdx.x;
    int wr = wid * 32;

    float c[2][8][4];
#pragma unroll
    for (int mt = 0; mt < 2; mt++)
#pragma unroll
        for (int nt = 0; nt < 8; nt++)
#pragma unroll
            for (int i = 0; i < 4; i++) c[mt][nt][i] = 0.f;

    float4 va[8], vb[2];
    // prefetch chunk 0
#pragma unroll
    for (int it = 0; it < 8; it++) {
        int idx = it * 256 + tid;
        int r = idx >> 3, q = idx & 7;
        int gm = blk * 256 + r;
        va[it] = (gm < M) ? A4[(size_t)gm * 128 + q]
                          : make_float4(0.f, 0.f, 0.f, 0.f);
    }
#pragma unroll
    for (int it = 0; it < 2; it++) {
        int idx = it * 256 + tid;
        int r = idx >> 3, q = idx & 7;
        vb[it] = B4[(size_t)r * 128 + q];
    }

    for (int kc = 0; kc < 16; kc++) {
        // commit prefetched chunk to smem
#pragma unroll
        for (int it = 0; it < 8; it++) {
            int idx = it * 256 + tid;
            int r = idx >> 3, q = idx & 7;
            *(float4*)(As + r * 36 + q * 4) = va[it];
        }
#pragma unroll
        for (int it = 0; it < 2; it++) {
            int idx = it * 256 + tid;
            int r = idx >> 3, q = idx & 7;
            float4 v = vb[it], h, l;
            h.x = fhi(v.x); l.x = fhi(v.x - h.x);
            h.y = fhi(v.y); l.y = fhi(v.y - h.y);
            h.z = fhi(v.z); l.z = fhi(v.z - h.z);
            h.w = fhi(v.w); l.w = fhi(v.w - h.w);
            *(float4*)(Bh + r * 36 + q * 4) = h;
            *(float4*)(Bl + r * 36 + q * 4) = l;
        }
        __syncthreads();

        if (kc < 15) {  // prefetch next chunk while mma runs
#pragma unroll
            for (int it = 0; it < 8; it++) {
                int idx = it * 256 + tid;
                int r = idx >> 3, q = idx & 7;
                int gm = blk * 256 + r;
                va[it] = (gm < M) ? A4[(size_t)gm * 128 + (kc + 1) * 8 + q]
                                  : make_float4(0.f, 0.f, 0.f, 0.f);
            }
#pragma unroll
            for (int it = 0; it < 2; it++) {
                int idx = it * 256 + tid;
                int r = idx >> 3, q = idx & 7;
                vb[it] = B4[(size_t)r * 128 + (kc + 1) * 8 + q];
            }
        }

#pragma unroll
        for (int s = 0; s < 4; s++)
            mma_step(As, 36, wr, s * 8, Bh, Bl, 36, s * 8, g, tg, c);
        __syncthreads();
    }

#pragma unroll
    for (int mt = 0; mt < 2; mt++) {
        int r0 = blk * 256 + wr + mt * 16 + g;
        int r1 = r0 + 8;
        float d0 = (r0 < M) ? deg[r0] : 1.f;
        float d1 = (r1 < M) ? deg[r1] : 1.f;
        float dv0 = (d0 > 0.f) ? rsqrtf(d0) : 0.f;
        float dv1 = (d1 > 0.f) ? rsqrtf(d1) : 0.f;
#pragma unroll
        for (int nt = 0; nt < 8; nt++) {
            int cb = nt * 8 + 2 * tg;
            if (r0 < M)
                *(float2*)(out + (size_t)r0 * 64 + cb) =
                    make_float2(dv0 * c[mt][nt][0], dv0 * c[mt][nt][1]);
            if (r1 < M)
                *(float2*)(out + (size_t)r1 * 64 + cb) =
                    make_float2(dv1 * c[mt][nt][2], dv1 * c[mt][nt][3]);
        }
    }
}

// ---------------------------------------------------------------------------
// tf32x3 GEMM body, K=64: out[m, ct*64+j] = sum_k A[m,k] B[ct*64+j, k]
// A resident (256x64, stride 68); full-K B tile per ct (single load, 2 syncs).
// ---------------------------------------------------------------------------
#define K64_SMEM ((256 * 68 + 2 * 64 * 68) * 4)

__device__ __forceinline__ void k64_gemm_body(
    const float4* __restrict__ A4, const float4* __restrict__ B4,
    float* __restrict__ out, int M, int ncols, int blk, float* sm)
{
    float* As = sm;
    float* Bh = sm + 256 * 68;
    float* Bl = Bh + 64 * 68;

    int tid = threadIdx.x, wid = tid >> 5, lane = tid & 31;
    int g = lane >> 2, tg = lane & 3;
    int wr = wid * 32;

#pragma unroll
    for (int it = 0; it < 16; it++) {
        int idx = it * 256 + tid;
        int r = idx >> 4, q = idx & 15;
        int gm = blk * 256 + r;
        float4 v = (gm < M) ? A4[(size_t)gm * 16 + q]
                            : make_float4(0.f, 0.f, 0.f, 0.f);
        *(float4*)(As + r * 68 + q * 4) = v;
    }
    __syncthreads();

    int ntilesc = ncols >> 6;
    for (int ct = 0; ct < ntilesc; ct++) {
        // B tile: 64 rows x full K=64, split hi/lo
#pragma unroll
        for (int it = 0; it < 4; it++) {
            int idx = it * 256 + tid;
            int r = idx >> 4, q = idx & 15;
            float4 v = B4[(size_t)(ct * 64 + r) * 16 + q];
            float4 h, l;
            h.x = fhi(v.x); l.x = fhi(v.x - h.x);
            h.y = fhi(v.y); l.y = fhi(v.y - h.y);
            h.z = fhi(v.z); l.z = fhi(v.z - h.z);
            h.w = fhi(v.w); l.w = fhi(v.w - h.w);
            *(float4*)(Bh + r * 68 + q * 4) = h;
            *(float4*)(Bl + r * 68 + q * 4) = l;
        }
        __syncthreads();

        float c[2][8][4];
#pragma unroll
        for (int mt = 0; mt < 2; mt++)
#pragma unroll
            for (int nt = 0; nt < 8; nt++)
#pragma unroll
                for (int i = 0; i < 4; i++) c[mt][nt][i] = 0.f;

#pragma unroll
        for (int s = 0; s < 8; s++)
            mma_step(As, 68, wr, s * 8, Bh, Bl, 68, s * 8, g, tg, c);

#pragma unroll
        for (int mt = 0; mt < 2; mt++) {
            int r0 = blk * 256 + wr + mt * 16 + g;
            int r1 = r0 + 8;
#pragma unroll
            for (int nt = 0; nt < 8; nt++) {
                int cb = ct * 64 + nt * 8 + 2 * tg;
                if (r0 < M)
                    *(float2*)(out + (size_t)r0 * ncols + cb) =
                        make_float2(c[mt][nt][0], c[mt][nt][1]);
                if (r1 < M)
                    *(float2*)(out + (size_t)r1 * ncols + cb) =
                        make_float2(c[mt][nt][2], c[mt][nt][3]);
            }
        }
        __syncthreads();
    }
}

__global__ __launch_bounds__(256) void mma_k64(
    const float4* __restrict__ A4, const float4* __restrict__ B4,
    float* __restrict__ out, int M, int ncols)
{
    extern __shared__ float sm[];
    k64_gemm_body(A4, B4, out, M, ncols, blockIdx.x, sm);
}

// ---------------------------------------------------------------------------
// CSR gather body (64-wide), unroll-4 for MLP
// ---------------------------------------------------------------------------
__device__ __forceinline__ void gather64_body(
    int gid, const int* __restrict__ start, const int* __restrict__ cnt,
    const float2* __restrict__ sw, const float4* __restrict__ feat4, int sf4,
    const float4* __restrict__ hs4, const float* __restrict__ dinv,
    const float* __restrict__ b1, float4* __restrict__ out4, int N, int mode)
{
    int d = gid >> 4;
    int q = gid & 15;
    if (d >= N) return;

    int j = start[d];
    int end = j + cnt[d];
    float4 acc = make_float4(0.f, 0.f, 0.f, 0.f);

    for (; j + 3 < end; j += 4) {
        float2 p0 = __ldg(&sw[j]);
        float2 p1 = __ldg(&sw[j + 1]);
        float2 p2 = __ldg(&sw[j + 2]);
        float2 p3 = __ldg(&sw[j + 3]);
        float4 v0 = feat4[(size_t)__float_as_int(p0.x) * sf4 + q];
        float4 v1 = feat4[(size_t)__float_as_int(p1.x) * sf4 + q];
        float4 v2 = feat4[(size_t)__float_as_int(p2.x) * sf4 + q];
        float4 v3 = feat4[(size_t)__float_as_int(p3.x) * sf4 + q];
        acc.x += p0.y * v0.x; acc.y += p0.y * v0.y;
        acc.z += p0.y * v0.z; acc.w += p0.y * v0.w;
        acc.x += p1.y * v1.x; acc.y += p1.y * v1.y;
        acc.z += p1.y * v1.z; acc.w += p1.y * v1.w;
        acc.x += p2.y * v2.x; acc.y += p2.y * v2.y;
        acc.z += p2.y * v2.z; acc.w += p2.y * v2.w;
        acc.x += p3.y * v3.x; acc.y += p3.y * v3.y;
        acc.z += p3.y * v3.z; acc.w += p3.y * v3.w;
    }
    for (; j < end; j++) {
        float2 p = __ldg(&sw[j]);
        float4 v = feat4[(size_t)__float_as_int(p.x) * sf4 + q];
        acc.x += p.y * v.x; acc.y += p.y * v.y;
        acc.z += p.y * v.z; acc.w += p.y * v.w;
    }

    int o = d * 16 + q;
    if (mode == 1) {
        float di = dinv[d];
        float4 h = hs4[o];
        float4 bb = ((const float4*)b1)[q];
        acc.x = fmaxf(di * (acc.x + h.x) + bb.x, 0.f);
        acc.y = fmaxf(di * (acc.y + h.y) + bb.y, 0.f);
        acc.z = fmaxf(di * (acc.z + h.z) + bb.z, 0.f);
        acc.w = fmaxf(di * (acc.w + h.w) + bb.w, 0.f);
    }
    out4[o] = acc;
}

__global__ void gather64(const int* __restrict__ start, const int* __restrict__ cnt,
                         const float2* __restrict__ sw, const float4* __restrict__ feat4,
                         int sf4, const float4* __restrict__ hs4,
                         const float* __restrict__ dinv, const float* __restrict__ b1,
                         float4* __restrict__ out4, int N, int mode) {
    int gid = blockIdx.x * 256 + threadIdx.x;
    gather64_body(gid, start, cnt, sw, feat4, sf4, hs4, dinv, b1, out4, N, mode);
}

// Merged kernel: gh GEMM (x@Whh^T) overlapped with gather64(m).
// Block mapping: every 17th block (b%17==0, b/17<Ggemm) runs the gemm path;
// the rest run the gather path. 17 = exact ratio (1 gemm : 16 gather blocks).
__global__ __launch_bounds__(256) void k_gather_gh(
    const int* __restrict__ start, const int* __restrict__ cnt,
    const float2* __restrict__ sw, const float4* __restrict__ m4,
    float4* __restrict__ acc4,
    const float4* __restrict__ x4, const float4* __restrict__ whh4,
    float* __restrict__ gh, int N, int Ggemm)
{
    extern __shared__ float sm[];
    int b = blockIdx.x;
    int gslot = b / 17;
    if ((b % 17 == 0) && (gslot < Ggemm)) {
        k64_gemm_body(x4, whh4, gh, N, 192, gslot, sm);
    } else {
        int ng = min(b / 17 + 1, Ggemm);
        int gid = (b - ng) * 256 + threadIdx.x;
        gather64_body(gid, start, cnt, sw, m4, 16, (const float4*)0,
                      (const float*)0, (const float*)0, acc4, N, 0);
    }
}

__global__ void gather16(const int* __restrict__ start, const int* __restrict__ cnt,
                         const float2* __restrict__ sw, const float4* __restrict__ feat4,
                         float4* __restrict__ out4, int N) {
    int gid = blockIdx.x * 256 + threadIdx.x;
    int d = gid >> 2;
    int q = gid & 3;
    if (d >= N) return;

    int j = start[d];
    int end = j + cnt[d];
    float4 acc = make_float4(0.f, 0.f, 0.f, 0.f);

    for (; j + 1 < end; j += 2) {
        float2 p0 = __ldg(&sw[j]);
        float2 p1 = __ldg(&sw[j + 1]);
        float4 v0 = feat4[(size_t)__float_as_int(p0.x) * 4 + q];
        float4 v1 = feat4[(size_t)__float_as_int(p1.x) * 4 + q];
        acc.x += p0.y * v0.x; acc.y += p0.y * v0.y;
        acc.z += p0.y * v0.z; acc.w += p0.y * v0.w;
        acc.x += p1.y * v1.x; acc.y += p1.y * v1.y;
        acc.z += p1.y * v1.z; acc.w += p1.y * v1.w;
    }
    if (j < end) {
        float2 p = __ldg(&sw[j]);
        float4 v = feat4[(size_t)__float_as_int(p.x) * 4 + q];
        acc.x += p.y * v.x; acc.y += p.y * v.y;
        acc.z += p.y * v.z; acc.w += p.y * v.w;
    }
    out4[d * 4 + q] = acc;
}

// ---------------------------------------------------------------------------
// GRU elementwise combine: x = GRU(gi, gh, x); both gi/gh stride 192
// ---------------------------------------------------------------------------
__global__ void gru_combine(const float* __restrict__ gi, const float* __restrict__ gh,
                            const float* __restrict__ bih, const float* __restrict__ bhh,
                            float* __restrict__ x, int n) {
    int i = blockIdx.x * 256 + threadIdx.x;
    if (i >= n * 64) return;
    int nd = i >> 6, f = i & 63;
    size_t b = (size_t)nd * 192;
    float r = 1.f / (1.f + expf(-(gi[b + f] + __ldg(&bih[f]) +
                                  gh[b + f] + __ldg(&bhh[f]))));
    float z = 1.f / (1.f + expf(-(gi[b + 64 + f] + __ldg(&bih[64 + f]) +
                                  gh[b + 64 + f] + __ldg(&bhh[64 + f]))));
    float ng = tanhf(gi[b + 128 + f] + __ldg(&bih[128 + f]) +
                     r * (gh[b + 128 + f] + __ldg(&bhh[128 + f])));
    x[i] = (1.f - z) * ng + z * x[i];
}

// ---------------------------------------------------------------------------
// GCN2 linear + finalize
// ---------------------------------------------------------------------------
__global__ void gemm_out16(const float* __restrict__ x, const float* __restrict__ W2,
                           const float* __restrict__ dinv, float* __restrict__ hs3,
                           int nrows) {
    __shared__ float w2s[64 * 16];
    int tid = threadIdx.x;
    for (int i = tid; i < 64 * 16; i += 256) w2s[i] = W2[i];
    __syncthreads();

    int node = blockIdx.x * 16 + (tid >> 4);
    int c = tid & 15;
    if (node >= nrows) return;
    const float* xr = x + (size_t)node * 64;
    float s = 0.f;
#pragma unroll
    for (int k = 0; k < 64; k++) s += xr[k] * w2s[k * 16 + c];
    hs3[(size_t)node * 16 + c] = dinv[node] * s;
}

__global__ void k_final(const float* __restrict__ acc3, const float* __restrict__ hs3,
                        const float* __restrict__ dinv, const float* __restrict__ b2,
                        float* __restrict__ out, int nrows) {
    int n = blockIdx.x * 256 + threadIdx.x;
    if (n >= nrows) return;
    float di = dinv[n];
    const float4* a4 = (const float4*)(acc3 + (size_t)n * 16);
    const float4* h4 = (const float4*)(hs3 + (size_t)n * 16);
    float v[16];
#pragma unroll
    for (int i = 0; i < 4; i++) {
        float4 a = a4[i];
        float4 h = h4[i];
        v[i * 4 + 0] = di * (a.x + h.x) + __ldg(&b2[i * 4 + 0]);
        v[i * 4 + 1] = di * (a.y + h.y) + __ldg(&b2[i * 4 + 1]);
        v[i * 4 + 2] = di * (a.z + h.z) + __ldg(&b2[i * 4 + 2]);
        v[i * 4 + 3] = di * (a.w + h.w) + __ldg(&b2[i * 4 + 3]);
    }
    float mx = v[0];
#pragma unroll
    for (int c = 1; c < 16; c++) mx = fmaxf(mx, v[c]);
    float sum = 0.f;
#pragma unroll
    for (int c = 0; c < 16; c++) sum += expf(v[c] - mx);
    float l = mx + logf(sum);
    float4* o4 = (float4*)(out + (size_t)n * 16);
#pragma unroll
    for (int i = 0; i < 4; i++) {
        float4 o;
        o.x = v[i * 4 + 0] - l;
        o.y = v[i * 4 + 1] - l;
        o.z = v[i * 4 + 2] - l;
        o.w = v[i * 4 + 3] - l;
        o4[i] = o;
    }
}

// ---------------------------------------------------------------------------
// Launch sequence (mma_k512 placed at launch slot 4 for ncu sampling)
// ---------------------------------------------------------------------------
extern "C" void kernel_launch(void* const* d_in, const int* in_sizes, int n_in,
                              void* d_out, int out_size) {
    const float* x   = (const float*)d_in[0];
    const int*   ei  = (const int*)d_in[1];
    const float* ew  = (const float*)d_in[2];
    const float* W1  = (const float*)d_in[3];
    const float* b1  = (const float*)d_in[4];
    const float* Wg  = (const float*)d_in[5];
    const float* Wih = (const float*)d_in[6];
    const float* Whh = (const float*)d_in[7];
    const float* bih = (const float*)d_in[8];
    const float* bhh = (const float*)d_in[9];
    const float* W2  = (const float*)d_in[10];
    const float* b2  = (const float*)d_in[11];
    float* out = (float*)d_out;

    const int N = in_sizes[0] / 512;
    const int E = in_sizes[2];
    const int* row = ei;
    const int* col = ei + E;

    float *p_deg, *p_dinv, *p_hs, *p_acc, *p_x, *p_hs3, *p_gi, *p_gh, *p_W1T, *p_WgT;
    int *p_cnt, *p_start, *p_cursor, *p_csum;
    float2* p_sw;
    cudaGetSymbolAddress((void**)&p_deg,    g_deg);
    cudaGetSymbolAddress((void**)&p_dinv,   g_dinv);
    cudaGetSymbolAddress((void**)&p_hs,     g_hs);
    cudaGetSymbolAddress((void**)&p_acc,    g_acc);
    cudaGetSymbolAddress((void**)&p_x,      g_x);
    cudaGetSymbolAddress((void**)&p_hs3,    g_hs3);
    cudaGetSymbolAddress((void**)&p_gi,     g_gi);
    cudaGetSymbolAddress((void**)&p_gh,     g_gh);
    cudaGetSymbolAddress((void**)&p_W1T,    g_W1T);
    cudaGetSymbolAddress((void**)&p_WgT,    g_WgT);
    cudaGetSymbolAddress((void**)&p_cnt,    g_cnt);
    cudaGetSymbolAddress((void**)&p_start,  g_start);
    cudaGetSymbolAddress((void**)&p_cursor, g_cursor);
    cudaGetSymbolAddress((void**)&p_csum,   g_csum);
    cudaGetSymbolAddress((void**)&p_sw,     g_sw);

    cudaFuncSetAttribute(mma_k512, cudaFuncAttributeMaxDynamicSharedMemorySize, K512_SMEM);
    cudaFuncSetAttribute(mma_k64,  cudaFuncAttributeMaxDynamicSharedMemorySize, K64_SMEM);
    cudaFuncSetAttribute(k_gather_gh, cudaFuncAttributeMaxDynamicSharedMemorySize, K64_SMEM);

    const int nblkN   = (N + 255) / 256;
    const int nblkE   = (E + 255) / 256;
    const int nblkM   = (N + 255) / 256;      // BM=256 tiles
    const int nblk16  = (N + 15) / 16;
    const int nchunks = (N + CHUNK - 1) / CHUNK;
    const int nblkG64 = (N * 16 + 255) / 256;
    const int nblkG16 = (N * 4 + 255) / 256;
    const int nblkNF  = (N * 64 + 255) / 256;

    // 1-3: prerequisites for the big GEMM
    k_T512<<<(512 * 64 + 255) / 256, 256>>>(W1, p_W1T);
    k_init<<<nblkN, 256>>>(p_deg, p_cnt, N);
    k_deg_hist<<<nblkE, 256>>>(col, ew, p_deg, p_cnt, E);
    // 4: GCN1 GEMM (ncu profiles this slot)
    mma_k512<<<nblkM, 256, K512_SMEM>>>((const float4*)x, (const float4*)p_W1T,
                                        p_hs, p_deg, N);
    // 5+: normalization, weight prep, CSR build
    k_dinv<<<nblkN, 256>>>(p_deg, p_dinv, N);
    k_T64<<<(2 * 64 * 64 + 255) / 256, 256>>>(Wg, p_WgT);
    k_scan_chunk<<<nchunks, CHUNK>>>(p_cnt, p_start, p_csum, N);
    k_scan_sums<<<1, 128>>>(p_csum, nchunks);
    k_scan_add<<<nblkN, 256>>>(p_start, p_cursor, p_csum, N);
    k_reorder<<<nblkE, 256>>>(row, col, ew, p_cursor, p_sw, E);

    // GCN1 gather (fuses relu/dinv/bias)
    gather64<<<nblkG64, 256>>>(p_start, p_cnt, p_sw, (const float4*)p_hs, 16,
                               (const float4*)p_hs, p_dinv, b1, (float4*)p_x, N, 1);

    // GatedGraphConv: 2 layers
    for (int l = 0; l < 2; l++) {
        // m = x @ Wg_l  (64 cols)
        mma_k64<<<nblkM, 256, K64_SMEM>>>((const float4*)p_x,
                                          (const float4*)(p_WgT + (size_t)l * 4096),
                                          p_hs, N, 64);
        // gather(m) overlapped with gh = x @ Whh^T
        k_gather_gh<<<nblkM + nblkG64, 256, K64_SMEM>>>(
            p_start, p_cnt, p_sw, (const float4*)p_hs, (float4*)p_acc,
            (const float4*)p_x, (const float4*)Whh, p_gh, N, nblkM);
        // gi = agg @ Wih^T
        mma_k64<<<nblkM, 256, K64_SMEM>>>((const float4*)p_acc, (const float4*)Wih,
                                          p_gi, N, 192);
        gru_combine<<<nblkNF, 256>>>(p_gi, p_gh, bih, bhh, p_x, N);
    }

    // GCN layer 2 + log_softmax
    gemm_out16<<<nblk16, 256>>>(p_x, W2, p_dinv, p_hs3, N);
    gather16<<<nblkG16, 256>>>(p_start, p_cnt, p_sw, (const float4*)p_hs3,
                               (float4*)p_acc, N);
    k_final<<<nblkN, 256>>>(p_acc, p_hs3, p_dinv, b2, out, N);
}

// round 7
// speedup vs baseline: 1.2083x; 1.2083x over previous
#include <cuda_runtime.h>
#include <cuda_fp16.h>
#include <math.h>
#include <stdint.h>

// ---------------------------------------------------------------------------
// Net_66468913873438: GCN(512->64)+ReLU -> GatedGraphConv(H=64, 2 layers)
//                     -> GCN(64->16) -> log_softmax
// N = 100000, E = 3200000.
// R7: revert gather/gemm merge (occupancy regression); fp16 feature copies
//     (written in GEMM epilogues) halve gather LTS traffic; fused
//     x@[Wg_l|Whh^T] GEMM per GGC layer.
// ---------------------------------------------------------------------------

#define NMAX 100000
#define EMAX 3200000
#define CHUNK 1024

// Scratch (static device globals).
__device__ __align__(16) float   g_deg   [NMAX];
__device__ __align__(16) float   g_dinv  [NMAX];
__device__ __align__(16) float   g_hs    [NMAX * 64];   // gemm1 out (fp32, self term)
__device__ __align__(16) __half  g_hsh   [NMAX * 64];   // fp16 copy for gather
__device__ __align__(16) __half  g_mh    [NMAX * 64];   // GGC messages (fp16)
__device__ __align__(16) float   g_acc   [NMAX * 64];   // gather accumulator
__device__ __align__(16) float   g_x     [NMAX * 64];   // node state
__device__ __align__(16) float   g_hs3   [NMAX * 16];
__device__ __align__(16) __half  g_hs3h  [NMAX * 16];
__device__ __align__(16) float   g_gi    [NMAX * 192];
__device__ __align__(16) float   g_gh    [NMAX * 192];
__device__ __align__(16) float   g_W1T   [64 * 512];
__device__ __align__(16) float   g_WB    [2 * 256 * 64]; // [WgT_l | Whh] K-major
// CSR
__device__ __align__(16) int     g_cnt   [NMAX];
__device__ __align__(16) int     g_start [NMAX];
__device__ __align__(16) int     g_cursor[NMAX];
__device__ __align__(16) int     g_csum  [128];
__device__ __align__(16) float2  g_sw    [EMAX];   // (src as int bits, weight)

// ---------------------------------------------------------------------------
// tf32 mma.sync helpers (sm_80 base ISA)
// ---------------------------------------------------------------------------
__device__ __forceinline__ float fhi(float a) {
    return __int_as_float(__float_as_int(a) & 0xFFFFE000u);
}

struct AFrag { uint32_t h[4]; uint32_t l[4]; };

__device__ __forceinline__ void mma8(float c[4], const uint32_t a[4],
                                     uint32_t b0, uint32_t b1) {
    asm volatile(
        "mma.sync.aligned.m16n8k8.row.col.f32.tf32.tf32.f32 "
        "{%0,%1,%2,%3}, {%4,%5,%6,%7}, {%8,%9}, {%0,%1,%2,%3};"
        : "+f"(c[0]), "+f"(c[1]), "+f"(c[2]), "+f"(c[3])
        : "r"(a[0]), "r"(a[1]), "r"(a[2]), "r"(a[3]), "r"(b0), "r"(b1));
}

__device__ __forceinline__ void load_afrag(const float* As, int stride, int rbase,
                                           int k0, int g, int tg, AFrag& f) {
    float a0 = As[(rbase + g) * stride + k0 + tg];
    float a1 = As[(rbase + g + 8) * stride + k0 + tg];
    float a2 = As[(rbase + g) * stride + k0 + tg + 4];
    float a3 = As[(rbase + g + 8) * stride + k0 + tg + 4];
    float h0 = fhi(a0), h1 = fhi(a1), h2 = fhi(a2), h3 = fhi(a3);
    f.h[0] = __float_as_uint(h0); f.l[0] = __float_as_uint(fhi(a0 - h0));
    f.h[1] = __float_as_uint(h1); f.l[1] = __float_as_uint(fhi(a1 - h1));
    f.h[2] = __float_as_uint(h2); f.l[2] = __float_as_uint(fhi(a2 - h2));
    f.h[3] = __float_as_uint(h3); f.l[3] = __float_as_uint(fhi(a3 - h3));
}

__device__ __forceinline__ void mma_step(const float* As, int astride, int wr,
                                         int ak0, const float* Bh, const float* Bl,
                                         int bstride, int bk0,
                                         int g, int tg, float c[2][8][4]) {
    AFrag fa[2];
    load_afrag(As, astride, wr, ak0, g, tg, fa[0]);
    load_afrag(As, astride, wr + 16, ak0, g, tg, fa[1]);
#pragma unroll
    for (int nt = 0; nt < 8; nt++) {
        int nr = (nt * 8 + g) * bstride + bk0;
        uint32_t bh0 = __float_as_uint(Bh[nr + tg]);
        uint32_t bh1 = __float_as_uint(Bh[nr + tg + 4]);
        uint32_t bl0 = __float_as_uint(Bl[nr + tg]);
        uint32_t bl1 = __float_as_uint(Bl[nr + tg + 4]);
#pragma unroll
        for (int mt = 0; mt < 2; mt++) {
            mma8(c[mt][nt], fa[mt].h, bh0, bh1);
            mma8(c[mt][nt], fa[mt].l, bh0, bh1);
            mma8(c[mt][nt], fa[mt].h, bl0, bl1);
        }
    }
}

// ---------------------------------------------------------------------------
// Small utility kernels
// ---------------------------------------------------------------------------
__global__ void k_init(float* __restrict__ deg, int* __restrict__ cnt, int n) {
    int i = blockIdx.x * 256 + threadIdx.x;
    if (i < n) { deg[i] = 1.0f; cnt[i] = 0; }
}
__global__ void k_deg_hist(const int* __restrict__ col, const float* __restrict__ w,
                           float* __restrict__ deg, int* __restrict__ cnt, int E) {
    int e = blockIdx.x * 256 + threadIdx.x;
    if (e < E) {
        int d = col[e];
        atomicAdd(&deg[d], w[e]);
        atomicAdd(&cnt[d], 1);
    }
}
__global__ void k_dinv(const float* __restrict__ deg, float* __restrict__ dinv, int n) {
    int i = blockIdx.x * 256 + threadIdx.x;
    if (i < n) {
        float d = deg[i];
        dinv[i] = (d > 0.f) ? rsqrtf(d) : 0.f;
    }
}
__global__ void k_T512(const float* __restrict__ W, float* __restrict__ WT) {
    int idx = blockIdx.x * 256 + threadIdx.x;
    if (idx >= 512 * 64) return;
    int k = idx / 64, j = idx % 64;
    WT[j * 512 + k] = W[idx];
}
// WB[l][j*64+k]: rows 0-63 = WgT_l (Wg[l][k][j]), rows 64-255 = Whh (K-major)
__global__ void k_buildWB(const float* __restrict__ Wg, const float* __restrict__ Whh,
                          float* __restrict__ WB) {
    int idx = blockIdx.x * 256 + threadIdx.x;
    if (idx >= 2 * 256 * 64) return;
    int l = idx / (256 * 64);
    int rem = idx % (256 * 64);
    int j = rem / 64, k = rem % 64;
    float v = (j < 64) ? Wg[l * 4096 + k * 64 + j] : Whh[(j - 64) * 64 + k];
    WB[idx] = v;
}

// ---------------------------------------------------------------------------
// CSR build
// ---------------------------------------------------------------------------
__global__ void k_scan_chunk(const int* __restrict__ cnt, int* __restrict__ start,
                             int* __restrict__ csum, int n) {
    __shared__ int sm[CHUNK];
    int base = blockIdx.x * CHUNK;
    int t = threadIdx.x;
    int v = (base + t < n) ? cnt[base + t] : 0;
    sm[t] = v;
    __syncthreads();
#pragma unroll
    for (int off = 1; off < CHUNK; off <<= 1) {
        int x = (t >= off) ? sm[t - off] : 0;
        __syncthreads();
        sm[t] += x;
        __syncthreads();
    }
    if (base + t < n) start[base + t] = sm[t] - v;
    if (t == CHUNK - 1) csum[blockIdx.x] = sm[t];
}
__global__ void k_scan_sums(int* __restrict__ csum, int nch) {
    __shared__ int s[128];
    int t = threadIdx.x;
    int v = (t < nch) ? csum[t] : 0;
    s[t] = v;
    __syncthreads();
#pragma unroll
    for (int off = 1; off < 128; off <<= 1) {
        int x = (t >= off) ? s[t - off] : 0;
        __syncthreads();
        s[t] += x;
        __syncthreads();
    }
    if (t < nch) csum[t] = s[t] - v;
}
__global__ void k_scan_add(int* __restrict__ start, int* __restrict__ cursor,
                           const int* __restrict__ csum, int n) {
    int i = blockIdx.x * 256 + threadIdx.x;
    if (i < n) {
        int s = start[i] + csum[i >> 10];
        start[i] = s;
        cursor[i] = s;
    }
}
__global__ void k_reorder(const int* __restrict__ row, const int* __restrict__ col,
                          const float* __restrict__ w, int* __restrict__ cursor,
                          float2* __restrict__ sw, int E) {
    int e = blockIdx.x * 256 + threadIdx.x;
    if (e >= E) return;
    int d = col[e];
    int pos = atomicAdd(&cursor[d], 1);
    sw[pos] = make_float2(__int_as_float(row[e]), w[e]);
}

// ---------------------------------------------------------------------------
// tf32x3 GEMM, K=512, prefetch-pipelined:
// hs[m,j] = rsqrt(deg[m]) * sum_k A[m,k] W1T[j,k]; also writes fp16 copy.
// ---------------------------------------------------------------------------
#define K512_SMEM ((256 * 36 + 2 * 64 * 36) * 4)

__global__ __launch_bounds__(256) void mma_k512(
    const float4* __restrict__ A4, const float4* __restrict__ B4,
    float* __restrict__ out, __half* __restrict__ outh,
    const float* __restrict__ deg, int M)
{
    extern __shared__ float sm[];
    float* As = sm;
    float* Bh = sm + 256 * 36;
    float* Bl = Bh + 64 * 36;

    int tid = threadIdx.x, wid = tid >> 5, lane = tid & 31;
    int g = lane >> 2, tg = lane & 3;
    int blk = blockIdx.x;
    int wr = wid * 32;

    float c[2][8][4];
#pragma unroll
    for (int mt = 0; mt < 2; mt++)
#pragma unroll
        for (int nt = 0; nt < 8; nt++)
#pragma unroll
            for (int i = 0; i < 4; i++) c[mt][nt][i] = 0.f;

    float4 va[8], vb[2];
#pragma unroll
    for (int it = 0; it < 8; it++) {
        int idx = it * 256 + tid;
        int r = idx >> 3, q = idx & 7;
        int gm = blk * 256 + r;
        va[it] = (gm < M) ? A4[(size_t)gm * 128 + q]
                          : make_float4(0.f, 0.f, 0.f, 0.f);
    }
#pragma unroll
    for (int it = 0; it < 2; it++) {
        int idx = it * 256 + tid;
        int r = idx >> 3, q = idx & 7;
        vb[it] = B4[(size_t)r * 128 + q];
    }

    for (int kc = 0; kc < 16; kc++) {
#pragma unroll
        for (int it = 0; it < 8; it++) {
            int idx = it * 256 + tid;
            int r = idx >> 3, q = idx & 7;
            *(float4*)(As + r * 36 + q * 4) = va[it];
        }
#pragma unroll
        for (int it = 0; it < 2; it++) {
            int idx = it * 256 + tid;
            int r = idx >> 3, q = idx & 7;
            float4 v = vb[it], h, l;
            h.x = fhi(v.x); l.x = fhi(v.x - h.x);
            h.y = fhi(v.y); l.y = fhi(v.y - h.y);
            h.z = fhi(v.z); l.z = fhi(v.z - h.z);
            h.w = fhi(v.w); l.w = fhi(v.w - h.w);
            *(float4*)(Bh + r * 36 + q * 4) = h;
            *(float4*)(Bl + r * 36 + q * 4) = l;
        }
        __syncthreads();

        if (kc < 15) {
#pragma unroll
            for (int it = 0; it < 8; it++) {
                int idx = it * 256 + tid;
                int r = idx >> 3, q = idx & 7;
                int gm = blk * 256 + r;
                va[it] = (gm < M) ? A4[(size_t)gm * 128 + (kc + 1) * 8 + q]
                                  : make_float4(0.f, 0.f, 0.f, 0.f);
            }
#pragma unroll
            for (int it = 0; it < 2; it++) {
                int idx = it * 256 + tid;
                int r = idx >> 3, q = idx & 7;
                vb[it] = B4[(size_t)r * 128 + (kc + 1) * 8 + q];
            }
        }

#pragma unroll
        for (int s = 0; s < 4; s++)
            mma_step(As, 36, wr, s * 8, Bh, Bl, 36, s * 8, g, tg, c);
        __syncthreads();
    }

#pragma unroll
    for (int mt = 0; mt < 2; mt++) {
        int r0 = blk * 256 + wr + mt * 16 + g;
        int r1 = r0 + 8;
        float d0 = (r0 < M) ? deg[r0] : 1.f;
        float d1 = (r1 < M) ? deg[r1] : 1.f;
        float dv0 = (d0 > 0.f) ? rsqrtf(d0) : 0.f;
        float dv1 = (d1 > 0.f) ? rsqrtf(d1) : 0.f;
#pragma unroll
        for (int nt = 0; nt < 8; nt++) {
            int cb = nt * 8 + 2 * tg;
            if (r0 < M) {
                float v0 = dv0 * c[mt][nt][0], v1 = dv0 * c[mt][nt][1];
                *(float2*)(out + (size_t)r0 * 64 + cb) = make_float2(v0, v1);
                *(__half2*)(outh + (size_t)r0 * 64 + cb) = __floats2half2_rn(v0, v1);
            }
            if (r1 < M) {
                float v2 = dv1 * c[mt][nt][2], v3 = dv1 * c[mt][nt][3];
                *(float2*)(out + (size_t)r1 * 64 + cb) = make_float2(v2, v3);
                *(__half2*)(outh + (size_t)r1 * 64 + cb) = __floats2half2_rn(v2, v3);
            }
        }
    }
}

// ---------------------------------------------------------------------------
// tf32x3 GEMM, K=64: first hcols columns -> outH (fp16, stride hcols),
// remaining -> outF (fp32, stride ncols-hcols). A resident in smem.
// ---------------------------------------------------------------------------
#define K64_SMEM ((256 * 68 + 2 * 64 * 68) * 4)

__global__ __launch_bounds__(256) void mma_k64(
    const float4* __restrict__ A4, const float4* __restrict__ B4,
    float* __restrict__ outF, __half* __restrict__ outH,
    int M, int ncols, int hcols)
{
    extern __shared__ float sm[];
    float* As = sm;
    float* Bh = sm + 256 * 68;
    float* Bl = Bh + 64 * 68;

    int tid = threadIdx.x, wid = tid >> 5, lane = tid & 31;
    int g = lane >> 2, tg = lane & 3;
    int blk = blockIdx.x;
    int wr = wid * 32;
    int fst = ncols - hcols;

#pragma unroll
    for (int it = 0; it < 16; it++) {
        int idx = it * 256 + tid;
        int r = idx >> 4, q = idx & 15;
        int gm = blk * 256 + r;
        float4 v = (gm < M) ? A4[(size_t)gm * 16 + q]
                            : make_float4(0.f, 0.f, 0.f, 0.f);
        *(float4*)(As + r * 68 + q * 4) = v;
    }
    __syncthreads();

    int ntilesc = ncols >> 6;
    for (int ct = 0; ct < ntilesc; ct++) {
#pragma unroll
        for (int it = 0; it < 4; it++) {
            int idx = it * 256 + tid;
            int r = idx >> 4, q = idx & 15;
            float4 v = B4[(size_t)(ct * 64 + r) * 16 + q];
            float4 h, l;
            h.x = fhi(v.x); l.x = fhi(v.x - h.x);
            h.y = fhi(v.y); l.y = fhi(v.y - h.y);
            h.z = fhi(v.z); l.z = fhi(v.z - h.z);
            h.w = fhi(v.w); l.w = fhi(v.w - h.w);
            *(float4*)(Bh + r * 68 + q * 4) = h;
            *(float4*)(Bl + r * 68 + q * 4) = l;
        }
        __syncthreads();

        float c[2][8][4];
#pragma unroll
        for (int mt = 0; mt < 2; mt++)
#pragma unroll
            for (int nt = 0; nt < 8; nt++)
#pragma unroll
                for (int i = 0; i < 4; i++) c[mt][nt][i] = 0.f;

#pragma unroll
        for (int s = 0; s < 8; s++)
            mma_step(As, 68, wr, s * 8, Bh, Bl, 68, s * 8, g, tg, c);

        bool toH = (ct * 64) < hcols;
#pragma unroll
        for (int mt = 0; mt < 2; mt++) {
            int r0 = blk * 256 + wr + mt * 16 + g;
            int r1 = r0 + 8;
#pragma unroll
            for (int nt = 0; nt < 8; nt++) {
                int cb = ct * 64 + nt * 8 + 2 * tg;
                if (toH) {
                    if (r0 < M)
                        *(__half2*)(outH + (size_t)r0 * hcols + cb) =
                            __floats2half2_rn(c[mt][nt][0], c[mt][nt][1]);
                    if (r1 < M)
                        *(__half2*)(outH + (size_t)r1 * hcols + cb) =
                            __floats2half2_rn(c[mt][nt][2], c[mt][nt][3]);
                } else {
                    int cbf = cb - hcols;
                    if (r0 < M)
                        *(float2*)(outF + (size_t)r0 * fst + cbf) =
                            make_float2(c[mt][nt][0], c[mt][nt][1]);
                    if (r1 < M)
                        *(float2*)(outF + (size_t)r1 * fst + cbf) =
                            make_float2(c[mt][nt][2], c[mt][nt][3]);
                }
            }
        }
        __syncthreads();
    }
}

// ---------------------------------------------------------------------------
// CSR gather, fp16 features, 64-wide: 16 lanes/dest, 4 halves (8B) per lane.
// mode 1: out = relu(dinv[d]*(acc + hs[d]) + b1)  (GCN1 finalize; hs fp32)
// ---------------------------------------------------------------------------
__global__ void gather64h(const int* __restrict__ start, const int* __restrict__ cnt,
                          const float2* __restrict__ sw, const __half* __restrict__ feat,
                          const float4* __restrict__ hs4, const float* __restrict__ dinv,
                          const float* __restrict__ b1, float4* __restrict__ out4,
                          int N, int mode) {
    int gid = blockIdx.x * 256 + threadIdx.x;
    int d = gid >> 4;
    int q = gid & 15;
    if (d >= N) return;

    int j = start[d];
    int end = j + cnt[d];
    float4 acc = make_float4(0.f, 0.f, 0.f, 0.f);

#pragma unroll 1
    for (; j + 3 < end; j += 4) {
        float2 p0 = __ldg(&sw[j]);
        float2 p1 = __ldg(&sw[j + 1]);
        float2 p2 = __ldg(&sw[j + 2]);
        float2 p3 = __ldg(&sw[j + 3]);
        uint2 u0 = *(const uint2*)(feat + (size_t)__float_as_int(p0.x) * 64 + q * 4);
        uint2 u1 = *(const uint2*)(feat + (size_t)__float_as_int(p1.x) * 64 + q * 4);
        uint2 u2 = *(const uint2*)(feat + (size_t)__float_as_int(p2.x) * 64 + q * 4);
        uint2 u3 = *(const uint2*)(feat + (size_t)__float_as_int(p3.x) * 64 + q * 4);
        float2 a0 = __half22float2(*(__half2*)&u0.x), b0 = __half22float2(*(__half2*)&u0.y);
        float2 a1 = __half22float2(*(__half2*)&u1.x), b1v = __half22float2(*(__half2*)&u1.y);
        float2 a2 = __half22float2(*(__half2*)&u2.x), b2 = __half22float2(*(__half2*)&u2.y);
        float2 a3 = __half22float2(*(__half2*)&u3.x), b3 = __half22float2(*(__half2*)&u3.y);
        acc.x += p0.y * a0.x; acc.y += p0.y * a0.y; acc.z += p0.y * b0.x; acc.w += p0.y * b0.y;
        acc.x += p1.y * a1.x; acc.y += p1.y * a1.y; acc.z += p1.y * b1v.x; acc.w += p1.y * b1v.y;
        acc.x += p2.y * a2.x; acc.y += p2.y * a2.y; acc.z += p2.y * b2.x; acc.w += p2.y * b2.y;
        acc.x += p3.y * a3.x; acc.y += p3.y * a3.y; acc.z += p3.y * b3.x; acc.w += p3.y * b3.y;
    }
    for (; j < end; j++) {
        float2 p = __ldg(&sw[j]);
        uint2 u = *(const uint2*)(feat + (size_t)__float_as_int(p.x) * 64 + q * 4);
        float2 a = __half22float2(*(__half2*)&u.x), b = __half22float2(*(__half2*)&u.y);
        acc.x += p.y * a.x; acc.y += p.y * a.y;
        acc.z += p.y * b.x; acc.w += p.y * b.y;
    }

    int o = d * 16 + q;
    if (mode == 1) {
        float di = dinv[d];
        float4 h = hs4[o];
        float4 bb = ((const float4*)b1)[q];
        acc.x = fmaxf(di * (acc.x + h.x) + bb.x, 0.f);
        acc.y = fmaxf(di * (acc.y + h.y) + bb.y, 0.f);
        acc.z = fmaxf(di * (acc.z + h.z) + bb.z, 0.f);
        acc.w = fmaxf(di * (acc.w + h.w) + bb.w, 0.f);
    }
    out4[o] = acc;
}

// 16-wide fp16 gather: 4 lanes/dest.
__global__ void gather16h(const int* __restrict__ start, const int* __restrict__ cnt,
                          const float2* __restrict__ sw, const __half* __restrict__ feat,
                          float4* __restrict__ out4, int N) {
    int gid = blockIdx.x * 256 + threadIdx.x;
    int d = gid >> 2;
    int q = gid & 3;
    if (d >= N) return;

    int j = start[d];
    int end = j + cnt[d];
    float4 acc = make_float4(0.f, 0.f, 0.f, 0.f);

    for (; j + 1 < end; j += 2) {
        float2 p0 = __ldg(&sw[j]);
        float2 p1 = __ldg(&sw[j + 1]);
        uint2 u0 = *(const uint2*)(feat + (size_t)__float_as_int(p0.x) * 16 + q * 4);
        uint2 u1 = *(const uint2*)(feat + (size_t)__float_as_int(p1.x) * 16 + q * 4);
        float2 a0 = __half22float2(*(__half2*)&u0.x), b0 = __half22float2(*(__half2*)&u0.y);
        float2 a1 = __half22float2(*(__half2*)&u1.x), b1v = __half22float2(*(__half2*)&u1.y);
        acc.x += p0.y * a0.x; acc.y += p0.y * a0.y; acc.z += p0.y * b0.x; acc.w += p0.y * b0.y;
        acc.x += p1.y * a1.x; acc.y += p1.y * a1.y; acc.z += p1.y * b1v.x; acc.w += p1.y * b1v.y;
    }
    if (j < end) {
        float2 p = __ldg(&sw[j]);
        uint2 u = *(const uint2*)(feat + (size_t)__float_as_int(p.x) * 16 + q * 4);
        float2 a = __half22float2(*(__half2*)&u.x), b = __half22float2(*(__half2*)&u.y);
        acc.x += p.y * a.x; acc.y += p.y * a.y;
        acc.z += p.y * b.x; acc.w += p.y * b.y;
    }
    out4[d * 4 + q] = acc;
}

// ---------------------------------------------------------------------------
// GRU elementwise combine: x = GRU(gi, gh, x); both stride 192
// ---------------------------------------------------------------------------
__global__ void gru_combine(const float* __restrict__ gi, const float* __restrict__ gh,
                            const float* __restrict__ bih, const float* __restrict__ bhh,
                            float* __restrict__ x, int n) {
    int i = blockIdx.x * 256 + threadIdx.x;
    if (i >= n * 64) return;
    int nd = i >> 6, f = i & 63;
    size_t b = (size_t)nd * 192;
    float r = 1.f / (1.f + expf(-(gi[b + f] + __ldg(&bih[f]) +
                                  gh[b + f] + __ldg(&bhh[f]))));
    float z = 1.f / (1.f + expf(-(gi[b + 64 + f] + __ldg(&bih[64 + f]) +
                                  gh[b + 64 + f] + __ldg(&bhh[64 + f]))));
    float ng = tanhf(gi[b + 128 + f] + __ldg(&bih[128 + f]) +
                     r * (gh[b + 128 + f] + __ldg(&bhh[128 + f])));
    x[i] = (1.f - z) * ng + z * x[i];
}

// ---------------------------------------------------------------------------
// GCN2 linear (writes fp32 + fp16) + finalize
// ---------------------------------------------------------------------------
__global__ void gemm_out16(const float* __restrict__ x, const float* __restrict__ W2,
                           const float* __restrict__ dinv, float* __restrict__ hs3,
                           __half* __restrict__ hs3h, int nrows) {
    __shared__ float w2s[64 * 16];
    int tid = threadIdx.x;
    for (int i = tid; i < 64 * 16; i += 256) w2s[i] = W2[i];
    __syncthreads();

    int node = blockIdx.x * 16 + (tid >> 4);
    int c = tid & 15;
    if (node >= nrows) return;
    const float* xr = x + (size_t)node * 64;
    float s = 0.f;
#pragma unroll
    for (int k = 0; k < 64; k++) s += xr[k] * w2s[k * 16 + c];
    float v = dinv[node] * s;
    hs3[(size_t)node * 16 + c] = v;
    hs3h[(size_t)node * 16 + c] = __float2half_rn(v);
}

__global__ void k_final(const float* __restrict__ acc3, const float* __restrict__ hs3,
                        const float* __restrict__ dinv, const float* __restrict__ b2,
                        float* __restrict__ out, int nrows) {
    int n = blockIdx.x * 256 + threadIdx.x;
    if (n >= nrows) return;
    float di = dinv[n];
    const float4* a4 = (const float4*)(acc3 + (size_t)n * 16);
    const float4* h4 = (const float4*)(hs3 + (size_t)n * 16);
    float v[16];
#pragma unroll
    for (int i = 0; i < 4; i++) {
        float4 a = a4[i];
        float4 h = h4[i];
        v[i * 4 + 0] = di * (a.x + h.x) + __ldg(&b2[i * 4 + 0]);
        v[i * 4 + 1] = di * (a.y + h.y) + __ldg(&b2[i * 4 + 1]);
        v[i * 4 + 2] = di * (a.z + h.z) + __ldg(&b2[i * 4 + 2]);
        v[i * 4 + 3] = di * (a.w + h.w) + __ldg(&b2[i * 4 + 3]);
    }
    float mx = v[0];
#pragma unroll
    for (int c = 1; c < 16; c++) mx = fmaxf(mx, v[c]);
    float sum = 0.f;
#pragma unroll
    for (int c = 0; c < 16; c++) sum += expf(v[c] - mx);
    float l = mx + logf(sum);
    float4* o4 = (float4*)(out + (size_t)n * 16);
#pragma unroll
    for (int i = 0; i < 4; i++) {
        float4 o;
        o.x = v[i * 4 + 0] - l;
        o.y = v[i * 4 + 1] - l;
        o.z = v[i * 4 + 2] - l;
        o.w = v[i * 4 + 3] - l;
        o4[i] = o;
    }
}

// ---------------------------------------------------------------------------
// Launch sequence (mma_k512 at slot 4 for ncu sampling)
// ---------------------------------------------------------------------------
extern "C" void kernel_launch(void* const* d_in, const int* in_sizes, int n_in,
                              void* d_out, int out_size) {
    const float* x   = (const float*)d_in[0];
    const int*   ei  = (const int*)d_in[1];
    const float* ew  = (const float*)d_in[2];
    const float* W1  = (const float*)d_in[3];
    const float* b1  = (const float*)d_in[4];
    const float* Wg  = (const float*)d_in[5];
    const float* Wih = (const float*)d_in[6];
    const float* Whh = (const float*)d_in[7];
    const float* bih = (const float*)d_in[8];
    const float* bhh = (const float*)d_in[9];
    const float* W2  = (const float*)d_in[10];
    const float* b2  = (const float*)d_in[11];
    float* out = (float*)d_out;

    const int N = in_sizes[0] / 512;
    const int E = in_sizes[2];
    const int* row = ei;
    const int* col = ei + E;

    float *p_deg, *p_dinv, *p_hs, *p_acc, *p_x, *p_hs3, *p_gi, *p_gh, *p_W1T, *p_WB;
    __half *p_hsh, *p_mh, *p_hs3h;
    int *p_cnt, *p_start, *p_cursor, *p_csum;
    float2* p_sw;
    cudaGetSymbolAddress((void**)&p_deg,    g_deg);
    cudaGetSymbolAddress((void**)&p_dinv,   g_dinv);
    cudaGetSymbolAddress((void**)&p_hs,     g_hs);
    cudaGetSymbolAddress((void**)&p_hsh,    g_hsh);
    cudaGetSymbolAddress((void**)&p_mh,     g_mh);
    cudaGetSymbolAddress((void**)&p_acc,    g_acc);
    cudaGetSymbolAddress((void**)&p_x,      g_x);
    cudaGetSymbolAddress((void**)&p_hs3,    g_hs3);
    cudaGetSymbolAddress((void**)&p_hs3h,   g_hs3h);
    cudaGetSymbolAddress((void**)&p_gi,     g_gi);
    cudaGetSymbolAddress((void**)&p_gh,     g_gh);
    cudaGetSymbolAddress((void**)&p_W1T,    g_W1T);
    cudaGetSymbolAddress((void**)&p_WB,     g_WB);
    cudaGetSymbolAddress((void**)&p_cnt,    g_cnt);
    cudaGetSymbolAddress((void**)&p_start,  g_start);
    cudaGetSymbolAddress((void**)&p_cursor, g_cursor);
    cudaGetSymbolAddress((void**)&p_csum,   g_csum);
    cudaGetSymbolAddress((void**)&p_sw,     g_sw);

    cudaFuncSetAttribute(mma_k512, cudaFuncAttributeMaxDynamicSharedMemorySize, K512_SMEM);
    cudaFuncSetAttribute(mma_k64,  cudaFuncAttributeMaxDynamicSharedMemorySize, K64_SMEM);

    const int nblkN   = (N + 255) / 256;
    const int nblkE   = (E + 255) / 256;
    const int nblkM   = (N + 255) / 256;
    const int nblk16  = (N + 15) / 16;
    const int nchunks = (N + CHUNK - 1) / CHUNK;
    const int nblkG64 = (N * 16 + 255) / 256;
    const int nblkG16 = (N * 4 + 255) / 256;
    const int nblkNF  = (N * 64 + 255) / 256;

    // 1-3: prerequisites for the big GEMM
    k_T512<<<(512 * 64 + 255) / 256, 256>>>(W1, p_W1T);
    k_init<<<nblkN, 256>>>(p_deg, p_cnt, N);
    k_deg_hist<<<nblkE, 256>>>(col, ew, p_deg, p_cnt, E);
    // 4: GCN1 GEMM (ncu slot)
    mma_k512<<<nblkM, 256, K512_SMEM>>>((const float4*)x, (const float4*)p_W1T,
                                        p_hs, p_hsh, p_deg, N);
    // 5+: normalization, weight prep, CSR build
    k_dinv<<<nblkN, 256>>>(p_deg, p_dinv, N);
    k_buildWB<<<(2 * 256 * 64 + 255) / 256, 256>>>(Wg, Whh, p_WB);
    k_scan_chunk<<<nchunks, CHUNK>>>(p_cnt, p_start, p_csum, N);
    k_scan_sums<<<1, 128>>>(p_csum, nchunks);
    k_scan_add<<<nblkN, 256>>>(p_start, p_cursor, p_csum, N);
    k_reorder<<<nblkE, 256>>>(row, col, ew, p_cursor, p_sw, E);

    // GCN1 gather (fp16 features, fuses relu/dinv/bias)
    gather64h<<<nblkG64, 256>>>(p_start, p_cnt, p_sw, p_hsh,
                                (const float4*)p_hs, p_dinv, b1, (float4*)p_x, N, 1);

    // GatedGraphConv: 2 layers
    for (int l = 0; l < 2; l++) {
        // [m | gh] = x @ [Wg_l | Whh^T]; m -> fp16 (cols 0:64), gh -> fp32 (192)
        mma_k64<<<nblkM, 256, K64_SMEM>>>((const float4*)p_x,
                                          (const float4*)(p_WB + (size_t)l * 256 * 64),
                                          p_gh, p_mh, N, 256, 64);
        // agg = gather(m)
        gather64h<<<nblkG64, 256>>>(p_start, p_cnt, p_sw, p_mh,
                                    (const float4*)0, (const float*)0, (const float*)0,
                                    (float4*)p_acc, N, 0);
        // gi = agg @ Wih^T (fp32, 192)
        mma_k64<<<nblkM, 256, K64_SMEM>>>((const float4*)p_acc, (const float4*)Wih,
                                          p_gi, (__half*)0, N, 192, 0);
        gru_combine<<<nblkNF, 256>>>(p_gi, p_gh, bih, bhh, p_x, N);
    }

    // GCN layer 2 + log_softmax
    gemm_out16<<<nblk16, 256>>>(p_x, W2, p_dinv, p_hs3, p_hs3h, N);
    gather16h<<<nblkG16, 256>>>(p_start, p_cnt, p_sw, p_hs3h, (float4*)p_acc, N);
    k_final<<<nblkN, 256>>>(p_acc, p_hs3, p_dinv, b2, out, N);
}

// round 8
// speedup vs baseline: 1.3576x; 1.1236x over previous
#include <cuda_runtime.h>
#include <cuda_fp16.h>
#include <cuda_bf16.h>
#include <math.h>
#include <stdint.h>

// ---------------------------------------------------------------------------
// Net_66468913873438: GCN(512->64)+ReLU -> GatedGraphConv(H=64, 2 layers)
//                     -> GCN(64->16) -> log_softmax
// N = 100000, E = 3200000.
// R8: bf16x3 mma.sync.m16n8k16 replaces tf32x3 m16n8k8 (half the MMA
//     instructions + half the B LDS traffic). fp16 gathers from R7 kept.
// ---------------------------------------------------------------------------

#define NMAX 100000
#define EMAX 3200000
#define CHUNK 1024

// Scratch (static device globals).
__device__ __align__(16) float   g_deg   [NMAX];
__device__ __align__(16) float   g_dinv  [NMAX];
__device__ __align__(16) float   g_hs    [NMAX * 64];   // gemm1 out (fp32 self term)
__device__ __align__(16) __half  g_hsh   [NMAX * 64];   // fp16 copy for gather
__device__ __align__(16) __half  g_mh    [NMAX * 64];   // GGC messages (fp16)
__device__ __align__(16) float   g_acc   [NMAX * 64];   // gather accumulator
__device__ __align__(16) float   g_x     [NMAX * 64];   // node state
__device__ __align__(16) float   g_hs3   [NMAX * 16];
__device__ __align__(16) __half  g_hs3h  [NMAX * 16];
__device__ __align__(16) float   g_gi    [NMAX * 192];
__device__ __align__(16) float   g_gh    [NMAX * 192];
__device__ __align__(16) float   g_W1T   [64 * 512];
__device__ __align__(16) float   g_WB    [2 * 256 * 64]; // [WgT_l | Whh] K-major
// CSR
__device__ __align__(16) int     g_cnt   [NMAX];
__device__ __align__(16) int     g_start [NMAX];
__device__ __align__(16) int     g_cursor[NMAX];
__device__ __align__(16) int     g_csum  [128];
__device__ __align__(16) float2  g_sw    [EMAX];

// ---------------------------------------------------------------------------
// bf16 mma.sync m16n8k16 helpers (sm_80 base ISA)
// ---------------------------------------------------------------------------
__device__ __forceinline__ void mma16(float c[4], const uint32_t a[4],
                                      uint32_t b0, uint32_t b1) {
    asm volatile(
        "mma.sync.aligned.m16n8k16.row.col.f32.bf16.bf16.f32 "
        "{%0,%1,%2,%3}, {%4,%5,%6,%7}, {%8,%9}, {%0,%1,%2,%3};"
        : "+f"(c[0]), "+f"(c[1]), "+f"(c[2]), "+f"(c[3])
        : "r"(a[0]), "r"(a[1]), "r"(a[2]), "r"(a[3]), "r"(b0), "r"(b1));
}

struct AF { uint32_t h[4]; uint32_t l[4]; };

// Split float2 -> packed bf16 hi + bf16 lo residual.
__device__ __forceinline__ void split2(float2 v, uint32_t& h, uint32_t& l) {
    __nv_bfloat162 hb = __floats2bfloat162_rn(v.x, v.y);
    float2 hf = __bfloat1622float2(hb);
    __nv_bfloat162 lb = __floats2bfloat162_rn(v.x - hf.x, v.y - hf.y);
    h = *(uint32_t*)&hb;
    l = *(uint32_t*)&lb;
}

// Build one m16k16 A fragment (hi+lo) from fp32 smem.
// a0={g,k0+2tg..+1} a1={g+8,..} a2={g,k0+2tg+8..+9} a3={g+8,..}
__device__ __forceinline__ void load_afrag16(const float* As, int stride, int rbase,
                                             int k0, int g, int tg, AF& f) {
    const float2* p0 = (const float2*)(As + (rbase + g) * stride + k0 + 2 * tg);
    const float2* p1 = (const float2*)(As + (rbase + g + 8) * stride + k0 + 2 * tg);
    split2(p0[0], f.h[0], f.l[0]);
    split2(p1[0], f.h[1], f.l[1]);
    split2(p0[4], f.h[2], f.l[2]);
    split2(p1[4], f.h[3], f.l[3]);
}

// one k16 step: warp tile 32 rows (2 m-frags) x 64 cols (8 n-frags), bf16x3.
// ak0: k offset in As (fp32). bk0: k offset in Bh/Bl (bf16, element units).
__device__ __forceinline__ void mma_step16(const float* As, int astride, int wr,
                                           int ak0, const __nv_bfloat16* Bh,
                                           const __nv_bfloat16* Bl, int bstride,
                                           int bk0, int g, int tg, float c[2][8][4]) {
    AF fa[2];
    load_afrag16(As, astride, wr, ak0, g, tg, fa[0]);
    load_afrag16(As, astride, wr + 16, ak0, g, tg, fa[1]);
#pragma unroll
    for (int nt = 0; nt < 8; nt++) {
        int nb = (nt * 8 + g) * bstride + bk0 + 2 * tg;
        uint32_t bh0 = *(const uint32_t*)(Bh + nb);
        uint32_t bh1 = *(const uint32_t*)(Bh + nb + 8);
        uint32_t bl0 = *(const uint32_t*)(Bl + nb);
        uint32_t bl1 = *(const uint32_t*)(Bl + nb + 8);
#pragma unroll
        for (int mt = 0; mt < 2; mt++) {
            mma16(c[mt][nt], fa[mt].h, bh0, bh1);
            mma16(c[mt][nt], fa[mt].l, bh0, bh1);
            mma16(c[mt][nt], fa[mt].h, bl0, bl1);
        }
    }
}

// Split a float4 (4 consecutive k) into bf16 hi/lo and store 8B each.
__device__ __forceinline__ void store_b_split(float4 v, __nv_bfloat16* Bh,
                                              __nv_bfloat16* Bl, int off) {
    uint32_t h01, l01, h23, l23;
    split2(make_float2(v.x, v.y), h01, l01);
    split2(make_float2(v.z, v.w), h23, l23);
    *(uint2*)(Bh + off) = make_uint2(h01, h23);
    *(uint2*)(Bl + off) = make_uint2(l01, l23);
}

// ---------------------------------------------------------------------------
// Small utility kernels
// ---------------------------------------------------------------------------
__global__ void k_init(float* __restrict__ deg, int* __restrict__ cnt, int n) {
    int i = blockIdx.x * 256 + threadIdx.x;
    if (i < n) { deg[i] = 1.0f; cnt[i] = 0; }
}
__global__ void k_deg_hist(const int* __restrict__ col, const float* __restrict__ w,
                           float* __restrict__ deg, int* __restrict__ cnt, int E) {
    int e = blockIdx.x * 256 + threadIdx.x;
    if (e < E) {
        int d = col[e];
        atomicAdd(&deg[d], w[e]);
        atomicAdd(&cnt[d], 1);
    }
}
__global__ void k_dinv(const float* __restrict__ deg, float* __restrict__ dinv, int n) {
    int i = blockIdx.x * 256 + threadIdx.x;
    if (i < n) {
        float d = deg[i];
        dinv[i] = (d > 0.f) ? rsqrtf(d) : 0.f;
    }
}
__global__ void k_T512(const float* __restrict__ W, float* __restrict__ WT) {
    int idx = blockIdx.x * 256 + threadIdx.x;
    if (idx >= 512 * 64) return;
    int k = idx / 64, j = idx % 64;
    WT[j * 512 + k] = W[idx];
}
__global__ void k_buildWB(const float* __restrict__ Wg, const float* __restrict__ Whh,
                          float* __restrict__ WB) {
    int idx = blockIdx.x * 256 + threadIdx.x;
    if (idx >= 2 * 256 * 64) return;
    int l = idx / (256 * 64);
    int rem = idx % (256 * 64);
    int j = rem / 64, k = rem % 64;
    float v = (j < 64) ? Wg[l * 4096 + k * 64 + j] : Whh[(j - 64) * 64 + k];
    WB[idx] = v;
}

// ---------------------------------------------------------------------------
// CSR build
// ---------------------------------------------------------------------------
__global__ void k_scan_chunk(const int* __restrict__ cnt, int* __restrict__ start,
                             int* __restrict__ csum, int n) {
    __shared__ int sm[CHUNK];
    int base = blockIdx.x * CHUNK;
    int t = threadIdx.x;
    int v = (base + t < n) ? cnt[base + t] : 0;
    sm[t] = v;
    __syncthreads();
#pragma unroll
    for (int off = 1; off < CHUNK; off <<= 1) {
        int x = (t >= off) ? sm[t - off] : 0;
        __syncthreads();
        sm[t] += x;
        __syncthreads();
    }
    if (base + t < n) start[base + t] = sm[t] - v;
    if (t == CHUNK - 1) csum[blockIdx.x] = sm[t];
}
__global__ void k_scan_sums(int* __restrict__ csum, int nch) {
    __shared__ int s[128];
    int t = threadIdx.x;
    int v = (t < nch) ? csum[t] : 0;
    s[t] = v;
    __syncthreads();
#pragma unroll
    for (int off = 1; off < 128; off <<= 1) {
        int x = (t >= off) ? s[t - off] : 0;
        __syncthreads();
        s[t] += x;
        __syncthreads();
    }
    if (t < nch) csum[t] = s[t] - v;
}
__global__ void k_scan_add(int* __restrict__ start, int* __restrict__ cursor,
                           const int* __restrict__ csum, int n) {
    int i = blockIdx.x * 256 + threadIdx.x;
    if (i < n) {
        int s = start[i] + csum[i >> 10];
        start[i] = s;
        cursor[i] = s;
    }
}
__global__ void k_reorder(const int* __restrict__ row, const int* __restrict__ col,
                          const float* __restrict__ w, int* __restrict__ cursor,
                          float2* __restrict__ sw, int E) {
    int e = blockIdx.x * 256 + threadIdx.x;
    if (e >= E) return;
    int d = col[e];
    int pos = atomicAdd(&cursor[d], 1);
    sw[pos] = make_float2(__int_as_float(row[e]), w[e]);
}

// ---------------------------------------------------------------------------
// bf16x3 GEMM, K=512, prefetch-pipelined:
// hs[m,j] = rsqrt(deg[m]) * sum_k A[m,k] W1T[j,k]; writes fp32 + fp16 copies.
// smem: As 256x36 fp32; Bh/Bl 64x40 bf16 (per 32-k chunk).
// ---------------------------------------------------------------------------
#define K512_SMEM (256 * 36 * 4 + 2 * 64 * 40 * 2)

__global__ __launch_bounds__(256) void mma_k512(
    const float4* __restrict__ A4, const float4* __restrict__ B4,
    float* __restrict__ out, __half* __restrict__ outh,
    const float* __restrict__ deg, int M)
{
    extern __shared__ float smf[];
    float* As = smf;
    __nv_bfloat16* Bh = (__nv_bfloat16*)(smf + 256 * 36);
    __nv_bfloat16* Bl = Bh + 64 * 40;

    int tid = threadIdx.x, wid = tid >> 5, lane = tid & 31;
    int g = lane >> 2, tg = lane & 3;
    int blk = blockIdx.x;
    int wr = wid * 32;

    float c[2][8][4];
#pragma unroll
    for (int mt = 0; mt < 2; mt++)
#pragma unroll
        for (int nt = 0; nt < 8; nt++)
#pragma unroll
            for (int i = 0; i < 4; i++) c[mt][nt][i] = 0.f;

    float4 va[8], vb[2];
#pragma unroll
    for (int it = 0; it < 8; it++) {
        int idx = it * 256 + tid;
        int r = idx >> 3, q = idx & 7;
        int gm = blk * 256 + r;
        va[it] = (gm < M) ? A4[(size_t)gm * 128 + q]
                          : make_float4(0.f, 0.f, 0.f, 0.f);
    }
#pragma unroll
    for (int it = 0; it < 2; it++) {
        int idx = it * 256 + tid;
        int r = idx >> 3, q = idx & 7;
        vb[it] = B4[(size_t)r * 128 + q];
    }

    for (int kc = 0; kc < 16; kc++) {
#pragma unroll
        for (int it = 0; it < 8; it++) {
            int idx = it * 256 + tid;
            int r = idx >> 3, q = idx & 7;
            *(float4*)(As + r * 36 + q * 4) = va[it];
        }
#pragma unroll
        for (int it = 0; it < 2; it++) {
            int idx = it * 256 + tid;
            int r = idx >> 3, q = idx & 7;
            store_b_split(vb[it], Bh, Bl, r * 40 + q * 4);
        }
        __syncthreads();

        if (kc < 15) {
#pragma unroll
            for (int it = 0; it < 8; it++) {
                int idx = it * 256 + tid;
                int r = idx >> 3, q = idx & 7;
                int gm = blk * 256 + r;
                va[it] = (gm < M) ? A4[(size_t)gm * 128 + (kc + 1) * 8 + q]
                                  : make_float4(0.f, 0.f, 0.f, 0.f);
            }
#pragma unroll
            for (int it = 0; it < 2; it++) {
                int idx = it * 256 + tid;
                int r = idx >> 3, q = idx & 7;
                vb[it] = B4[(size_t)r * 128 + (kc + 1) * 8 + q];
            }
        }

#pragma unroll
        for (int s = 0; s < 2; s++)
            mma_step16(As, 36, wr, s * 16, Bh, Bl, 40, s * 16, g, tg, c);
        __syncthreads();
    }

#pragma unroll
    for (int mt = 0; mt < 2; mt++) {
        int r0 = blk * 256 + wr + mt * 16 + g;
        int r1 = r0 + 8;
        float d0 = (r0 < M) ? deg[r0] : 1.f;
        float d1 = (r1 < M) ? deg[r1] : 1.f;
        float dv0 = (d0 > 0.f) ? rsqrtf(d0) : 0.f;
        float dv1 = (d1 > 0.f) ? rsqrtf(d1) : 0.f;
#pragma unroll
        for (int nt = 0; nt < 8; nt++) {
            int cb = nt * 8 + 2 * tg;
            if (r0 < M) {
                float v0 = dv0 * c[mt][nt][0], v1 = dv0 * c[mt][nt][1];
                *(float2*)(out + (size_t)r0 * 64 + cb) = make_float2(v0, v1);
                *(__half2*)(outh + (size_t)r0 * 64 + cb) = __floats2half2_rn(v0, v1);
            }
            if (r1 < M) {
                float v2 = dv1 * c[mt][nt][2], v3 = dv1 * c[mt][nt][3];
                *(float2*)(out + (size_t)r1 * 64 + cb) = make_float2(v2, v3);
                *(__half2*)(outh + (size_t)r1 * 64 + cb) = __floats2half2_rn(v2, v3);
            }
        }
    }
}

// ---------------------------------------------------------------------------
// bf16x3 GEMM, K=64: first hcols columns -> outH (fp16, stride hcols),
// remaining -> outF (fp32, stride ncols-hcols). A resident in smem (fp32),
// B tile split to bf16 (stride 72) per 64-column tile.
// ---------------------------------------------------------------------------
#define K64_SMEM (256 * 68 * 4 + 2 * 64 * 72 * 2)

__global__ __launch_bounds__(256) void mma_k64(
    const float4* __restrict__ A4, const float4* __restrict__ B4,
    float* __restrict__ outF, __half* __restrict__ outH,
    int M, int ncols, int hcols)
{
    extern __shared__ float smf[];
    float* As = smf;
    __nv_bfloat16* Bh = (__nv_bfloat16*)(smf + 256 * 68);
    __nv_bfloat16* Bl = Bh + 64 * 72;

    int tid = threadIdx.x, wid = tid >> 5, lane = tid & 31;
    int g = lane >> 2, tg = lane & 3;
    int blk = blockIdx.x;
    int wr = wid * 32;
    int fst = ncols - hcols;

#pragma unroll
    for (int it = 0; it < 16; it++) {
        int idx = it * 256 + tid;
        int r = idx >> 4, q = idx & 15;
        int gm = blk * 256 + r;
        float4 v = (gm < M) ? A4[(size_t)gm * 16 + q]
                            : make_float4(0.f, 0.f, 0.f, 0.f);
        *(float4*)(As + r * 68 + q * 4) = v;
    }
    __syncthreads();

    int ntilesc = ncols >> 6;
    for (int ct = 0; ct < ntilesc; ct++) {
#pragma unroll
        for (int it = 0; it < 4; it++) {
            int idx = it * 256 + tid;
            int r = idx >> 4, q = idx & 15;
            float4 v = B4[(size_t)(ct * 64 + r) * 16 + q];
            store_b_split(v, Bh, Bl, r * 72 + q * 4);
        }
        __syncthreads();

        float c[2][8][4];
#pragma unroll
        for (int mt = 0; mt < 2; mt++)
#pragma unroll
            for (int nt = 0; nt < 8; nt++)
#pragma unroll
                for (int i = 0; i < 4; i++) c[mt][nt][i] = 0.f;

#pragma unroll
        for (int s = 0; s < 4; s++)
            mma_step16(As, 68, wr, s * 16, Bh, Bl, 72, s * 16, g, tg, c);

        bool toH = (ct * 64) < hcols;
#pragma unroll
        for (int mt = 0; mt < 2; mt++) {
            int r0 = blk * 256 + wr + mt * 16 + g;
            int r1 = r0 + 8;
#pragma unroll
            for (int nt = 0; nt < 8; nt++) {
                int cb = ct * 64 + nt * 8 + 2 * tg;
                if (toH) {
                    if (r0 < M)
                        *(__half2*)(outH + (size_t)r0 * hcols + cb) =
                            __floats2half2_rn(c[mt][nt][0], c[mt][nt][1]);
                    if (r1 < M)
                        *(__half2*)(outH + (size_t)r1 * hcols + cb) =
                            __floats2half2_rn(c[mt][nt][2], c[mt][nt][3]);
                } else {
                    int cbf = cb - hcols;
                    if (r0 < M)
                        *(float2*)(outF + (size_t)r0 * fst + cbf) =
                            make_float2(c[mt][nt][0], c[mt][nt][1]);
                    if (r1 < M)
                        *(float2*)(outF + (size_t)r1 * fst + cbf) =
                            make_float2(c[mt][nt][2], c[mt][nt][3]);
                }
            }
        }
        __syncthreads();
    }
}

// ---------------------------------------------------------------------------
// CSR gather, fp16 features, 64-wide: 16 lanes/dest, 4 halves (8B) per lane.
// mode 1: out = relu(dinv[d]*(acc + hs[d]) + b1)
// ---------------------------------------------------------------------------
__global__ void gather64h(const int* __restrict__ start, const int* __restrict__ cnt,
                          const float2* __restrict__ sw, const __half* __restrict__ feat,
                          const float4* __restrict__ hs4, const float* __restrict__ dinv,
                          const float* __restrict__ b1, float4* __restrict__ out4,
                          int N, int mode) {
    int gid = blockIdx.x * 256 + threadIdx.x;
    int d = gid >> 4;
    int q = gid & 15;
    if (d >= N) return;

    int j = start[d];
    int end = j + cnt[d];
    float4 acc = make_float4(0.f, 0.f, 0.f, 0.f);

#pragma unroll 1
    for (; j + 3 < end; j += 4) {
        float2 p0 = __ldg(&sw[j]);
        float2 p1 = __ldg(&sw[j + 1]);
        float2 p2 = __ldg(&sw[j + 2]);
        float2 p3 = __ldg(&sw[j + 3]);
        uint2 u0 = *(const uint2*)(feat + (size_t)__float_as_int(p0.x) * 64 + q * 4);
        uint2 u1 = *(const uint2*)(feat + (size_t)__float_as_int(p1.x) * 64 + q * 4);
        uint2 u2 = *(const uint2*)(feat + (size_t)__float_as_int(p2.x) * 64 + q * 4);
        uint2 u3 = *(const uint2*)(feat + (size_t)__float_as_int(p3.x) * 64 + q * 4);
        float2 a0 = __half22float2(*(__half2*)&u0.x), b0 = __half22float2(*(__half2*)&u0.y);
        float2 a1 = __half22float2(*(__half2*)&u1.x), b1v = __half22float2(*(__half2*)&u1.y);
        float2 a2 = __half22float2(*(__half2*)&u2.x), b2 = __half22float2(*(__half2*)&u2.y);
        float2 a3 = __half22float2(*(__half2*)&u3.x), b3 = __half22float2(*(__half2*)&u3.y);
        acc.x += p0.y * a0.x; acc.y += p0.y * a0.y; acc.z += p0.y * b0.x; acc.w += p0.y * b0.y;
        acc.x += p1.y * a1.x; acc.y += p1.y * a1.y; acc.z += p1.y * b1v.x; acc.w += p1.y * b1v.y;
        acc.x += p2.y * a2.x; acc.y += p2.y * a2.y; acc.z += p2.y * b2.x; acc.w += p2.y * b2.y;
        acc.x += p3.y * a3.x; acc.y += p3.y * a3.y; acc.z += p3.y * b3.x; acc.w += p3.y * b3.y;
    }
    for (; j < end; j++) {
        float2 p = __ldg(&sw[j]);
        uint2 u = *(const uint2*)(feat + (size_t)__float_as_int(p.x) * 64 + q * 4);
        float2 a = __half22float2(*(__half2*)&u.x), b = __half22float2(*(__half2*)&u.y);
        acc.x += p.y * a.x; acc.y += p.y * a.y;
        acc.z += p.y * b.x; acc.w += p.y * b.y;
    }

    int o = d * 16 + q;
    if (mode == 1) {
        float di = dinv[d];
        float4 h = hs4[o];
        float4 bb = ((const float4*)b1)[q];
        acc.x = fmaxf(di * (acc.x + h.x) + bb.x, 0.f);
        acc.y = fmaxf(di * (acc.y + h.y) + bb.y, 0.f);
        acc.z = fmaxf(di * (acc.z + h.z) + bb.z, 0.f);
        acc.w = fmaxf(di * (acc.w + h.w) + bb.w, 0.f);
    }
    out4[o] = acc;
}

__global__ void gather16h(const int* __restrict__ start, const int* __restrict__ cnt,
                          const float2* __restrict__ sw, const __half* __restrict__ feat,
                          float4* __restrict__ out4, int N) {
    int gid = blockIdx.x * 256 + threadIdx.x;
    int d = gid >> 2;
    int q = gid & 3;
    if (d >= N) return;

    int j = start[d];
    int end = j + cnt[d];
    float4 acc = make_float4(0.f, 0.f, 0.f, 0.f);

    for (; j + 1 < end; j += 2) {
        float2 p0 = __ldg(&sw[j]);
        float2 p1 = __ldg(&sw[j + 1]);
        uint2 u0 = *(const uint2*)(feat + (size_t)__float_as_int(p0.x) * 16 + q * 4);
        uint2 u1 = *(const uint2*)(feat + (size_t)__float_as_int(p1.x) * 16 + q * 4);
        float2 a0 = __half22float2(*(__half2*)&u0.x), b0 = __half22float2(*(__half2*)&u0.y);
        float2 a1 = __half22float2(*(__half2*)&u1.x), b1v = __half22float2(*(__half2*)&u1.y);
        acc.x += p0.y * a0.x; acc.y += p0.y * a0.y; acc.z += p0.y * b0.x; acc.w += p0.y * b0.y;
        acc.x += p1.y * a1.x; acc.y += p1.y * a1.y; acc.z += p1.y * b1v.x; acc.w += p1.y * b1v.y;
    }
    if (j < end) {
        float2 p = __ldg(&sw[j]);
        uint2 u = *(const uint2*)(feat + (size_t)__float_as_int(p.x) * 16 + q * 4);
        float2 a = __half22float2(*(__half2*)&u.x), b = __half22float2(*(__half2*)&u.y);
        acc.x += p.y * a.x; acc.y += p.y * a.y;
        acc.z += p.y * b.x; acc.w += p.y * b.y;
    }
    out4[d * 4 + q] = acc;
}

// ---------------------------------------------------------------------------
// GRU elementwise combine: x = GRU(gi, gh, x); both stride 192
// ---------------------------------------------------------------------------
__global__ void gru_combine(const float* __restrict__ gi, const float* __restrict__ gh,
                            const float* __restrict__ bih, const float* __restrict__ bhh,
                            float* __restrict__ x, int n) {
    int i = blockIdx.x * 256 + threadIdx.x;
    if (i >= n * 64) return;
    int nd = i >> 6, f = i & 63;
    size_t b = (size_t)nd * 192;
    float r = 1.f / (1.f + expf(-(gi[b + f] + __ldg(&bih[f]) +
                                  gh[b + f] + __ldg(&bhh[f]))));
    float z = 1.f / (1.f + expf(-(gi[b + 64 + f] + __ldg(&bih[64 + f]) +
                                  gh[b + 64 + f] + __ldg(&bhh[64 + f]))));
    float ng = tanhf(gi[b + 128 + f] + __ldg(&bih[128 + f]) +
                     r * (gh[b + 128 + f] + __ldg(&bhh[128 + f])));
    x[i] = (1.f - z) * ng + z * x[i];
}

// ---------------------------------------------------------------------------
// GCN2 linear (writes fp32 + fp16) + finalize
// ---------------------------------------------------------------------------
__global__ void gemm_out16(const float* __restrict__ x, const float* __restrict__ W2,
                           const float* __restrict__ dinv, float* __restrict__ hs3,
                           __half* __restrict__ hs3h, int nrows) {
    __shared__ float w2s[64 * 16];
    int tid = threadIdx.x;
    for (int i = tid; i < 64 * 16; i += 256) w2s[i] = W2[i];
    __syncthreads();

    int node = blockIdx.x * 16 + (tid >> 4);
    int c = tid & 15;
    if (node >= nrows) return;
    const float* xr = x + (size_t)node * 64;
    float s = 0.f;
#pragma unroll
    for (int k = 0; k < 64; k++) s += xr[k] * w2s[k * 16 + c];
    float v = dinv[node] * s;
    hs3[(size_t)node * 16 + c] = v;
    hs3h[(size_t)node * 16 + c] = __float2half_rn(v);
}

__global__ void k_final(const float* __restrict__ acc3, const float* __restrict__ hs3,
                        const float* __restrict__ dinv, const float* __restrict__ b2,
                        float* __restrict__ out, int nrows) {
    int n = blockIdx.x * 256 + threadIdx.x;
    if (n >= nrows) return;
    float di = dinv[n];
    const float4* a4 = (const float4*)(acc3 + (size_t)n * 16);
    const float4* h4 = (const float4*)(hs3 + (size_t)n * 16);
    float v[16];
#pragma unroll
    for (int i = 0; i < 4; i++) {
        float4 a = a4[i];
        float4 h = h4[i];
        v[i * 4 + 0] = di * (a.x + h.x) + __ldg(&b2[i * 4 + 0]);
        v[i * 4 + 1] = di * (a.y + h.y) + __ldg(&b2[i * 4 + 1]);
        v[i * 4 + 2] = di * (a.z + h.z) + __ldg(&b2[i * 4 + 2]);
        v[i * 4 + 3] = di * (a.w + h.w) + __ldg(&b2[i * 4 + 3]);
    }
    float mx = v[0];
#pragma unroll
    for (int c = 1; c < 16; c++) mx = fmaxf(mx, v[c]);
    float sum = 0.f;
#pragma unroll
    for (int c = 0; c < 16; c++) sum += expf(v[c] - mx);
    float l = mx + logf(sum);
    float4* o4 = (float4*)(out + (size_t)n * 16);
#pragma unroll
    for (int i = 0; i < 4; i++) {
        float4 o;
        o.x = v[i * 4 + 0] - l;
        o.y = v[i * 4 + 1] - l;
        o.z = v[i * 4 + 2] - l;
        o.w = v[i * 4 + 3] - l;
        o4[i] = o;
    }
}

// ---------------------------------------------------------------------------
// Launch sequence (mma_k512 at slot 4 for ncu sampling)
// ---------------------------------------------------------------------------
extern "C" void kernel_launch(void* const* d_in, const int* in_sizes, int n_in,
                              void* d_out, int out_size) {
    const float* x   = (const float*)d_in[0];
    const int*   ei  = (const int*)d_in[1];
    const float* ew  = (const float*)d_in[2];
    const float* W1  = (const float*)d_in[3];
    const float* b1  = (const float*)d_in[4];
    const float* Wg  = (const float*)d_in[5];
    const float* Wih = (const float*)d_in[6];
    const float* Whh = (const float*)d_in[7];
    const float* bih = (const float*)d_in[8];
    const float* bhh = (const float*)d_in[9];
    const float* W2  = (const float*)d_in[10];
    const float* b2  = (const float*)d_in[11];
    float* out = (float*)d_out;

    const int N = in_sizes[0] / 512;
    const int E = in_sizes[2];
    const int* row = ei;
    const int* col = ei + E;

    float *p_deg, *p_dinv, *p_hs, *p_acc, *p_x, *p_hs3, *p_gi, *p_gh, *p_W1T, *p_WB;
    __half *p_hsh, *p_mh, *p_hs3h;
    int *p_cnt, *p_start, *p_cursor, *p_csum;
    float2* p_sw;
    cudaGetSymbolAddress((void**)&p_deg,    g_deg);
    cudaGetSymbolAddress((void**)&p_dinv,   g_dinv);
    cudaGetSymbolAddress((void**)&p_hs,     g_hs);
    cudaGetSymbolAddress((void**)&p_hsh,    g_hsh);
    cudaGetSymbolAddress((void**)&p_mh,     g_mh);
    cudaGetSymbolAddress((void**)&p_acc,    g_acc);
    cudaGetSymbolAddress((void**)&p_x,      g_x);
    cudaGetSymbolAddress((void**)&p_hs3,    g_hs3);
    cudaGetSymbolAddress((void**)&p_hs3h,   g_hs3h);
    cudaGetSymbolAddress((void**)&p_gi,     g_gi);
    cudaGetSymbolAddress((void**)&p_gh,     g_gh);
    cudaGetSymbolAddress((void**)&p_W1T,    g_W1T);
    cudaGetSymbolAddress((void**)&p_WB,     g_WB);
    cudaGetSymbolAddress((void**)&p_cnt,    g_cnt);
    cudaGetSymbolAddress((void**)&p_start,  g_start);
    cudaGetSymbolAddress((void**)&p_cursor, g_cursor);
    cudaGetSymbolAddress((void**)&p_csum,   g_csum);
    cudaGetSymbolAddress((void**)&p_sw,     g_sw);

    cudaFuncSetAttribute(mma_k512, cudaFuncAttributeMaxDynamicSharedMemorySize, K512_SMEM);
    cudaFuncSetAttribute(mma_k64,  cudaFuncAttributeMaxDynamicSharedMemorySize, K64_SMEM);

    const int nblkN   = (N + 255) / 256;
    const int nblkE   = (E + 255) / 256;
    const int nblkM   = (N + 255) / 256;
    const int nblk16  = (N + 15) / 16;
    const int nchunks = (N + CHUNK - 1) / CHUNK;
    const int nblkG64 = (N * 16 + 255) / 256;
    const int nblkG16 = (N * 4 + 255) / 256;
    const int nblkNF  = (N * 64 + 255) / 256;

    // 1-3: prerequisites for the big GEMM
    k_T512<<<(512 * 64 + 255) / 256, 256>>>(W1, p_W1T);
    k_init<<<nblkN, 256>>>(p_deg, p_cnt, N);
    k_deg_hist<<<nblkE, 256>>>(col, ew, p_deg, p_cnt, E);
    // 4: GCN1 GEMM (ncu slot)
    mma_k512<<<nblkM, 256, K512_SMEM>>>((const float4*)x, (const float4*)p_W1T,
                                        p_hs, p_hsh, p_deg, N);
    // 5+: normalization, weight prep, CSR build
    k_dinv<<<nblkN, 256>>>(p_deg, p_dinv, N);
    k_buildWB<<<(2 * 256 * 64 + 255) / 256, 256>>>(Wg, Whh, p_WB);
    k_scan_chunk<<<nchunks, CHUNK>>>(p_cnt, p_start, p_csum, N);
    k_scan_sums<<<1, 128>>>(p_csum, nchunks);
    k_scan_add<<<nblkN, 256>>>(p_start, p_cursor, p_csum, N);
    k_reorder<<<nblkE, 256>>>(row, col, ew, p_cursor, p_sw, E);

    // GCN1 gather (fp16 features, fuses relu/dinv/bias)
    gather64h<<<nblkG64, 256>>>(p_start, p_cnt, p_sw, p_hsh,
                                (const float4*)p_hs, p_dinv, b1, (float4*)p_x, N, 1);

    // GatedGraphConv: 2 layers
    for (int l = 0; l < 2; l++) {
        // [m | gh] = x @ [Wg_l | Whh^T]; m -> fp16 (cols 0:64), gh -> fp32 (192)
        mma_k64<<<nblkM, 256, K64_SMEM>>>((const float4*)p_x,
                                          (const float4*)(p_WB + (size_t)l * 256 * 64),
                                          p_gh, p_mh, N, 256, 64);
        // agg = gather(m)
        gather64h<<<nblkG64, 256>>>(p_start, p_cnt, p_sw, p_mh,
                                    (const float4*)0, (const float*)0, (const float*)0,
                                    (float4*)p_acc, N, 0);
        // gi = agg @ Wih^T (fp32, 192)
        mma_k64<<<nblkM, 256, K64_SMEM>>>((const float4*)p_acc, (const float4*)Wih,
                                          p_gi, (__half*)0, N, 192, 0);
        gru_combine<<<nblkNF, 256>>>(p_gi, p_gh, bih, bhh, p_x, N);
    }

    // GCN layer 2 + log_softmax
    gemm_out16<<<nblk16, 256>>>(p_x, W2, p_dinv, p_hs3, p_hs3h, N);
    gather16h<<<nblkG16, 256>>>(p_start, p_cnt, p_sw, p_hs3h, (float4*)p_acc, N);
    k_final<<<nblkN, 256>>>(p_acc, p_hs3, p_dinv, b2, out, N);
}